// round 8
// baseline (speedup 1.0000x reference)
#include <cuda_runtime.h>
#include <cstdint>

// Gather 2048 columns (8 groups x 8 slices x 32 cols) from a [16384, 4096] f32
// matrix into d_out laid out as 8 concatenated [16384, 256] group blocks.
//
// R8 (= R7 fixed): persistent single-wave grid-stride kernel. 512 CTAs
// (~3.5/SM on 148 SMs) -> exactly one wave, no wave transitions / tail
// drain. 2^22 32-byte chunks total; 2^17 threads; 32 chunks per thread as
// 8 iterations of a 4-wide front-batched load/store group (MLP~4/thread).
// Loads via inline-asm ld.global.nc.v4.b64 (__ldg lacks a ulonglong4
// overload; evict hints proven inert in R5/R6).
//
// Per-chunk index math (idx in [0, 2^22)):
//   g   = idx >> 19          (2^19 chunks per group)
//   row = (idx >> 5) & 16383 (32 chunks per 256-float output row)
//   c8  = idx & 31
//   in  = row*512 + g*64 + (c8>>2)*8 + (c8&3)  (input row = 512 chunks)

__device__ __forceinline__ ulonglong4 ldg_nc256(const ulonglong4* p)
{
    ulonglong4 v;
    asm("ld.global.nc.v4.b64 {%0,%1,%2,%3}, [%4];"
        : "=l"(v.x), "=l"(v.y), "=l"(v.z), "=l"(v.w) : "l"(p));
    return v;
}

__global__ void __launch_bounds__(256)
slice_cat_kernel(const ulonglong4* __restrict__ in8, ulonglong4* __restrict__ out8)
{
    // 2^17 threads; stride 2^17 chunks per k-step, 2^19 per iteration
    const uint32_t tid0 = blockIdx.x * 256u + threadIdx.x;

    for (uint32_t i = 0; i < 8; ++i) {
        const uint32_t base = i * 524288u + tid0;

        uint32_t in_idx[4];
#pragma unroll
        for (int k = 0; k < 4; ++k) {
            const uint32_t idx = base + k * 131072u;
            const uint32_t g   = idx >> 19;
            const uint32_t row = (idx >> 5) & 16383u;
            const uint32_t c8  = idx & 31u;
            in_idx[k] = row * 512u + g * 64u + (c8 >> 2) * 8u + (c8 & 3u);
        }

        ulonglong4 v[4];
#pragma unroll
        for (int k = 0; k < 4; ++k)
            v[k] = ldg_nc256(&in8[in_idx[k]]);

#pragma unroll
        for (int k = 0; k < 4; ++k)
            out8[base + k * 131072u] = v[k];
    }
}

extern "C" void kernel_launch(void* const* d_in, const int* in_sizes, int n_in,
                              void* d_out, int out_size)
{
    (void)in_sizes; (void)n_in; (void)out_size;
    const ulonglong4* in8 = (const ulonglong4*)d_in[0];
    ulonglong4* out8 = (ulonglong4*)d_out;

    // single wave: 512 blocks x 256 threads = 2^17 threads
    slice_cat_kernel<<<512, 256>>>(in8, out8);
}

// round 9
// speedup vs baseline: 1.2402x; 1.2402x over previous
#include <cuda_runtime.h>
#include <cstdint>

// Gather 2048 columns (8 groups x 8 slices x 32 cols) from a [16384, 4096] f32
// matrix into d_out laid out as 8 concatenated [16384, 256] group blocks.
//
// FINAL (R9 = best measured config, from R2): one thread per float4, x4
// unrolled with front-batched independent LDG.128s (MLP~4/thread), 8192
// blocks x 256 threads (-> ~8 resident CTAs/SM, 64 warps/SM driving SM-wide
// memory-level parallelism; R8 showed concurrency, not wave count, is what
// sustains bandwidth). Stores perfectly contiguous STG.128; loads are
// 128B-aligned full-sector chunks.
//
// Converged at the sustained mixed read+write DRAM roofline:
// 268 MB compulsory traffic @ ~5.9 TB/s -> ~45 us. Falsified levers: L2
// evict hints (inert without access-policy window), cross-replay L2 pinning,
// 256-bit vectorization (neutral), single-wave persistent grid (regression
// via occupancy loss).
//
// Index math (per float4 output index idx in [0, 2^23)):
//   g    = idx >> 20            (8 groups, 2^20 float4 each)
//   row  = (idx >> 6) & 16383   (64 float4 per output row)
//   c4   = idx & 63
//   in   = row*1024 + g*128 + (c4>>3)*16 + (c4&7)

__global__ void __launch_bounds__(256)
slice_cat_kernel(const float4* __restrict__ in4, float4* __restrict__ out4)
{
    const uint32_t base = blockIdx.x * 1024u + threadIdx.x;

    uint32_t in_idx[4];
#pragma unroll
    for (int k = 0; k < 4; ++k) {
        const uint32_t idx = base + k * 256u;
        const uint32_t g   = idx >> 20;
        const uint32_t row = (idx >> 6) & 16383u;
        const uint32_t c4  = idx & 63u;
        in_idx[k] = row * 1024u + g * 128u + (c4 >> 3) * 16u + (c4 & 7u);
    }

    float4 v[4];
#pragma unroll
    for (int k = 0; k < 4; ++k)
        v[k] = __ldg(&in4[in_idx[k]]);

#pragma unroll
    for (int k = 0; k < 4; ++k)
        out4[base + k * 256u] = v[k];
}

extern "C" void kernel_launch(void* const* d_in, const int* in_sizes, int n_in,
                              void* d_out, int out_size)
{
    (void)in_sizes; (void)n_in; (void)out_size;
    const float4* in4 = (const float4*)d_in[0];
    float4* out4 = (float4*)d_out;

    // total float4 = 2^23; 1024 per block -> 8192 blocks
    slice_cat_kernel<<<8192, 256>>>(in4, out4);
}